// round 3
// baseline (speedup 1.0000x reference)
#include <cuda_runtime.h>
#include <cuda_bf16.h>

#define Hd 512
#define Bd 128
#define Td 2048
#define Md (Bd * Td)

#define BM 128
#define BN 128
#define BK 16
#define NTHREADS 256
#define XS_STRIDE (BM + 4)   // 132: keeps 16B alignment, reduces STS conflicts
#define NKSTEPS (Hd / BK)    // 32

// Allocation-free scratch (__device__ globals are the sanctioned workaround)
__device__ float g_Wsum[Hd * Hd];
__device__ float g_bsum[Hd];
__device__ float g_score[Md];

// ---------------------------------------------------------------------------
// Kernel 1: Wsum = Wa_w + Ua_w ; bsum = Wa_b + Ua_b
// ---------------------------------------------------------------------------
__global__ void prep_kernel(const float* __restrict__ Wa_w,
                            const float* __restrict__ Ua_w,
                            const float* __restrict__ Wa_b,
                            const float* __restrict__ Ua_b) {
    int i = blockIdx.x * blockDim.x + threadIdx.x;
    if (i < Hd * Hd) g_Wsum[i] = Wa_w[i] + Ua_w[i];
    if (i < Hd)      g_bsum[i] = Wa_b[i] + Ua_b[i];
}

// ---------------------------------------------------------------------------
// Kernel 2: score[r] = Va_b + sum_n Va[n] * tanh( sum_k x[r,k]*Wsum[n,k] + bsum[n] )
// 128x128x16 double-buffered SGEMM, 8x8 register micro-tile, fused
// tanh-dot epilogue per 128-wide N chunk. Grid: Md/BM = 2048 blocks.
// ---------------------------------------------------------------------------
__global__ __launch_bounds__(NTHREADS, 2)
void score_kernel(const float* __restrict__ x,
                  const float* __restrict__ Va_w,
                  const float* __restrict__ Va_b) {
    __shared__ float xs[2][BK][XS_STRIDE];   // k-transposed x tiles
    __shared__ float ws[2][BK][XS_STRIDE];   // k-transposed Wsum tiles
    __shared__ float bs_s[Hd];
    __shared__ float va_s[Hd];
    __shared__ float red[BM * 16];

    const int tid  = threadIdx.x;
    const int tx   = tid & 15;            // cols tx*8..tx*8+7
    const int ty   = tid >> 4;            // rows ty*8..ty*8+7
    const int row0 = blockIdx.x * BM;

    for (int i = tid; i < Hd; i += NTHREADS) {
        bs_s[i] = g_bsum[i];
        va_s[i] = Va_w[i];
    }

    // Loader mapping: 512 float4 per tile, 2 per thread (rows lrow, lrow+64)
    const int lrow = tid >> 2;            // 0..63
    const int lk4  = (tid & 3) << 2;      // 0,4,8,12

    const float* xbase = x + (size_t)row0 * Hd + lk4;

    float rowpart[8];
#pragma unroll
    for (int i = 0; i < 8; i++) rowpart[i] = 0.f;

    __syncthreads();

    for (int nb = 0; nb < Hd; nb += BN) {
        const float* wbase = g_Wsum + (size_t)nb * Hd + lk4;

        float acc[8][8];
#pragma unroll
        for (int i = 0; i < 8; i++)
#pragma unroll
            for (int j = 0; j < 8; j++) acc[i][j] = 0.f;

        // ---- prologue: load k-tile 0 into buffer 0 ----
        {
            float4 vx0 = *(const float4*)&xbase[(size_t)lrow * Hd];
            float4 vx1 = *(const float4*)&xbase[(size_t)(lrow + 64) * Hd];
            float4 vw0 = *(const float4*)&wbase[(size_t)lrow * Hd];
            float4 vw1 = *(const float4*)&wbase[(size_t)(lrow + 64) * Hd];
            xs[0][lk4 + 0][lrow] = vx0.x; xs[0][lk4 + 1][lrow] = vx0.y;
            xs[0][lk4 + 2][lrow] = vx0.z; xs[0][lk4 + 3][lrow] = vx0.w;
            xs[0][lk4 + 0][lrow + 64] = vx1.x; xs[0][lk4 + 1][lrow + 64] = vx1.y;
            xs[0][lk4 + 2][lrow + 64] = vx1.z; xs[0][lk4 + 3][lrow + 64] = vx1.w;
            ws[0][lk4 + 0][lrow] = vw0.x; ws[0][lk4 + 1][lrow] = vw0.y;
            ws[0][lk4 + 2][lrow] = vw0.z; ws[0][lk4 + 3][lrow] = vw0.w;
            ws[0][lk4 + 0][lrow + 64] = vw1.x; ws[0][lk4 + 1][lrow + 64] = vw1.y;
            ws[0][lk4 + 2][lrow + 64] = vw1.z; ws[0][lk4 + 3][lrow + 64] = vw1.w;
        }
        __syncthreads();

        for (int kbi = 0; kbi < NKSTEPS; kbi++) {
            const int cur = kbi & 1;
            const int nxt = cur ^ 1;
            const bool has_next = (kbi + 1) < NKSTEPS;

            // ---- issue next tile's global loads early (hide LDG latency) ----
            float4 vx0, vx1, vw0, vw1;
            if (has_next) {
                const int kb = (kbi + 1) * BK;
                vx0 = *(const float4*)&xbase[(size_t)lrow * Hd + kb];
                vx1 = *(const float4*)&xbase[(size_t)(lrow + 64) * Hd + kb];
                vw0 = *(const float4*)&wbase[(size_t)lrow * Hd + kb];
                vw1 = *(const float4*)&wbase[(size_t)(lrow + 64) * Hd + kb];
            }

            // ---- compute on current buffer ----
#pragma unroll
            for (int k = 0; k < BK; k++) {
                float4 a0 = *(const float4*)&xs[cur][k][ty * 8];
                float4 a1 = *(const float4*)&xs[cur][k][ty * 8 + 4];
                float4 b0 = *(const float4*)&ws[cur][k][tx * 8];
                float4 b1 = *(const float4*)&ws[cur][k][tx * 8 + 4];
                float a[8] = {a0.x, a0.y, a0.z, a0.w, a1.x, a1.y, a1.z, a1.w};
                float b[8] = {b0.x, b0.y, b0.z, b0.w, b1.x, b1.y, b1.z, b1.w};
#pragma unroll
                for (int i = 0; i < 8; i++)
#pragma unroll
                    for (int j = 0; j < 8; j++)
                        acc[i][j] = fmaf(a[i], b[j], acc[i][j]);
            }

            // ---- store next tile into the other buffer, one sync ----
            if (has_next) {
                xs[nxt][lk4 + 0][lrow] = vx0.x; xs[nxt][lk4 + 1][lrow] = vx0.y;
                xs[nxt][lk4 + 2][lrow] = vx0.z; xs[nxt][lk4 + 3][lrow] = vx0.w;
                xs[nxt][lk4 + 0][lrow + 64] = vx1.x; xs[nxt][lk4 + 1][lrow + 64] = vx1.y;
                xs[nxt][lk4 + 2][lrow + 64] = vx1.z; xs[nxt][lk4 + 3][lrow + 64] = vx1.w;
                ws[nxt][lk4 + 0][lrow] = vw0.x; ws[nxt][lk4 + 1][lrow] = vw0.y;
                ws[nxt][lk4 + 2][lrow] = vw0.z; ws[nxt][lk4 + 3][lrow] = vw0.w;
                ws[nxt][lk4 + 0][lrow + 64] = vw1.x; ws[nxt][lk4 + 1][lrow + 64] = vw1.y;
                ws[nxt][lk4 + 2][lrow + 64] = vw1.z; ws[nxt][lk4 + 3][lrow + 64] = vw1.w;
            }
            __syncthreads();
        }

        // ---- fused epilogue: tanh + Va dot for this 128-wide N chunk ----
#pragma unroll
        for (int j = 0; j < 8; j++) {
            int n = nb + tx * 8 + j;
            float bsv = bs_s[n];
            float vav = va_s[n];
#pragma unroll
            for (int i = 0; i < 8; i++)
                rowpart[i] = fmaf(tanhf(acc[i][j] + bsv), vav, rowpart[i]);
        }
    }

    // Cross-thread reduction: 16 threads (tx) share each of the 128 rows
#pragma unroll
    for (int i = 0; i < 8; i++)
        red[(ty * 8 + i) * 16 + tx] = rowpart[i];
    __syncthreads();

    if (tid < BM) {
        float s = 0.f;
#pragma unroll
        for (int t = 0; t < 16; t++) s += red[tid * 16 + t];
        g_score[row0 + tid] = s + Va_b[0];
    }
}

// ---------------------------------------------------------------------------
// Kernel 3: softmax over T per batch row. Grid: B blocks, 256 threads.
// ---------------------------------------------------------------------------
__global__ __launch_bounds__(256)
void softmax_kernel(float* __restrict__ out_w) {
    __shared__ float sred[256];
    const int b = blockIdx.x;
    const int tid = threadIdx.x;
    const float* s = g_score + (size_t)b * Td;
    float* w = out_w + (size_t)b * Td;

    float m = -1e30f;
    for (int t = tid; t < Td; t += 256) m = fmaxf(m, s[t]);
    sred[tid] = m;
    __syncthreads();
    for (int o = 128; o > 0; o >>= 1) {
        if (tid < o) sred[tid] = fmaxf(sred[tid], sred[tid + o]);
        __syncthreads();
    }
    m = sred[0];
    __syncthreads();

    float sum = 0.f;
    for (int t = tid; t < Td; t += 256) {
        float e = __expf(s[t] - m);
        w[t] = e;
        sum += e;
    }
    sred[tid] = sum;
    __syncthreads();
    for (int o = 128; o > 0; o >>= 1) {
        if (tid < o) sred[tid] += sred[tid + o];
        __syncthreads();
    }
    float inv = 1.f / sred[0];
    for (int t = tid; t < Td; t += 256) w[t] *= inv;
}

// ---------------------------------------------------------------------------
// Kernel 4: context[b,h] = sum_t w[b,t] * x[b,t,h]
// Grid: (Hd/256, B), 256 threads.
// ---------------------------------------------------------------------------
__global__ __launch_bounds__(256)
void context_kernel(const float* __restrict__ x,
                    const float* __restrict__ w,
                    float* __restrict__ ctx) {
    __shared__ float ws_[Td];
    const int b = blockIdx.y;
    const int h = blockIdx.x * 256 + threadIdx.x;

    for (int t = threadIdx.x; t < Td; t += 256)
        ws_[t] = w[(size_t)b * Td + t];
    __syncthreads();

    const float* xb = x + (size_t)b * Td * Hd + h;
    float a0 = 0.f, a1 = 0.f, a2 = 0.f, a3 = 0.f;
    for (int t = 0; t < Td; t += 4) {
        a0 = fmaf(ws_[t + 0], xb[(size_t)(t + 0) * Hd], a0);
        a1 = fmaf(ws_[t + 1], xb[(size_t)(t + 1) * Hd], a1);
        a2 = fmaf(ws_[t + 2], xb[(size_t)(t + 2) * Hd], a2);
        a3 = fmaf(ws_[t + 3], xb[(size_t)(t + 3) * Hd], a3);
    }
    ctx[(size_t)b * Hd + h] = ((a0 + a1) + (a2 + a3));
}

// ---------------------------------------------------------------------------
// Launch
// ---------------------------------------------------------------------------
extern "C" void kernel_launch(void* const* d_in, const int* in_sizes, int n_in,
                              void* d_out, int out_size) {
    const float* x    = (const float*)d_in[0];   // [B,T,H]
    const float* Wa_w = (const float*)d_in[1];   // [H,H]
    const float* Wa_b = (const float*)d_in[2];   // [H]
    const float* Ua_w = (const float*)d_in[3];   // [H,H]
    const float* Ua_b = (const float*)d_in[4];   // [H]
    const float* Va_w = (const float*)d_in[5];   // [1,H]
    const float* Va_b = (const float*)d_in[6];   // [1]

    float* out_ctx = (float*)d_out;              // [B,H]
    float* out_w   = (float*)d_out + Bd * Hd;    // [B,T]

    prep_kernel<<<(Hd * Hd + 255) / 256, 256>>>(Wa_w, Ua_w, Wa_b, Ua_b);
    score_kernel<<<Md / BM, NTHREADS>>>(x, Va_w, Va_b);
    softmax_kernel<<<Bd, 256>>>(out_w);
    context_kernel<<<dim3(Hd / 256, Bd), 256>>>(x, out_w, out_ctx);
}

// round 5
// speedup vs baseline: 1.5259x; 1.5259x over previous
#include <cuda_runtime.h>
#include <cuda_bf16.h>
#include <cstdint>

#define Hd 512
#define Bd 128
#define Td 2048
#define Md (Bd * Td)
#define BM 128

// ---------------- smem layout (bytes) ----------------
#define SM_BS   0
#define SM_VA   2048
#define SM_RED  4096
#define SM_XH   4608
#define SM_XL   (SM_XH + 18432)
#define SM_WH   (SM_XL + 18432)
#define SM_WL   (SM_WH + 18432)
#define SMEM_TOTAL (SM_WL + 18432)   // 78336 bytes
#define TSTRIDE 144                  // 72 bf16 per padded tile row

__device__ __nv_bfloat16 g_Whi[Hd * Hd];
__device__ __nv_bfloat16 g_Wlo[Hd * Hd];
__device__ float g_bsum[Hd];
__device__ float g_score[Md];

__device__ __forceinline__ uint32_t smem_to_u32(const void* p) {
    uint32_t a;
    asm("{ .reg .u64 t; cvta.to.shared.u64 t, %1; cvt.u32.u64 %0, t; }" : "=r"(a) : "l"(p));
    return a;
}
__device__ __forceinline__ void ldsm_x4(uint32_t& r0, uint32_t& r1, uint32_t& r2,
                                        uint32_t& r3, uint32_t addr) {
    asm volatile("ldmatrix.sync.aligned.m8n8.x4.shared.b16 {%0,%1,%2,%3}, [%4];"
                 : "=r"(r0), "=r"(r1), "=r"(r2), "=r"(r3) : "r"(addr));
}
__device__ __forceinline__ void mma16816(float* d, const uint32_t* a, const uint32_t* b) {
    asm volatile("mma.sync.aligned.m16n8k16.row.col.f32.bf16.bf16.f32 "
                 "{%0,%1,%2,%3}, {%4,%5,%6,%7}, {%8,%9}, {%0,%1,%2,%3};"
                 : "+f"(d[0]), "+f"(d[1]), "+f"(d[2]), "+f"(d[3])
                 : "r"(a[0]), "r"(a[1]), "r"(a[2]), "r"(a[3]), "r"(b[0]), "r"(b[1]));
}

// ---------------------------------------------------------------------------
// Kernel 1: Wsum -> bf16 hi/lo split; bsum.
// ---------------------------------------------------------------------------
__global__ void prep_kernel(const float* __restrict__ Wa_w, const float* __restrict__ Ua_w,
                            const float* __restrict__ Wa_b, const float* __restrict__ Ua_b) {
    int i = blockIdx.x * blockDim.x + threadIdx.x;
    if (i < Hd * Hd) {
        float w = Wa_w[i] + Ua_w[i];
        __nv_bfloat16 h = __float2bfloat16(w);
        g_Whi[i] = h;
        g_Wlo[i] = __float2bfloat16(w - __bfloat162float(h));
    }
    if (i < Hd) g_bsum[i] = Wa_b[i] + Ua_b[i];
}

// ---------------------------------------------------------------------------
// Kernel 2: score GEMM via mma.sync bf16 (3-pass hi/lo), fused tanh/Va epi.
// Block = 128 rows x N512 (4 chunks of 128). 8 warps as 4(M)x2(N), warp tile
// 32x64. K streamed in 8 segs of 64 fp32 (x converted to hi/lo in smem).
// ---------------------------------------------------------------------------
__global__ __launch_bounds__(256, 2)
void score_mma(const float* __restrict__ x,
               const float* __restrict__ Va_w,
               const float* __restrict__ Va_b) {
    extern __shared__ char smem[];
    const uint32_t sb = smem_to_u32(smem);
    float* bs_s = (float*)(smem + SM_BS);
    float* va_s = (float*)(smem + SM_VA);
    float* red  = (float*)(smem + SM_RED);

    const int tid = threadIdx.x, lane = tid & 31, wid = tid >> 5;
    const int warp_m = wid & 3, warp_n = wid >> 2;
    const int row0 = blockIdx.x * BM;

    for (int i = tid; i < Hd; i += 256) { bs_s[i] = g_bsum[i]; va_s[i] = Va_w[i]; }
    if (tid < BM) red[tid] = 0.f;

    // ldmatrix per-lane addressing
    const uint32_t a_row  = (uint32_t)(lane & 15);
    const uint32_t a_colb = (uint32_t)(((lane >> 4) & 1) * 16);
    const uint32_t b_row  = (uint32_t)((lane & 7) + (lane & 8));
    const uint32_t b_colb = a_colb;

    float rowpart[2][2] = {{0.f, 0.f}, {0.f, 0.f}};
    __syncthreads();

    for (int nb = 0; nb < 4; nb++) {
        float acc[2][8][4];
#pragma unroll
        for (int mi = 0; mi < 2; mi++)
#pragma unroll
            for (int ni = 0; ni < 8; ni++)
#pragma unroll
                for (int q = 0; q < 4; q++) acc[mi][ni][q] = 0.f;

        for (int kt = 0; kt < 8; kt++) {
            const int kb = kt * 64;

            // x tile: 128 rows x 64 fp32 -> bf16 hi/lo (padded rows)
#pragma unroll
            for (int it = 0; it < 8; it++) {
                int idx = tid + it * 256;       // 0..2047 float4s
                int r = idx >> 4, c4 = idx & 15;
                float4 v = *(const float4*)&x[(size_t)(row0 + r) * Hd + kb + c4 * 4];
                __nv_bfloat16 h0 = __float2bfloat16(v.x), h1 = __float2bfloat16(v.y);
                __nv_bfloat16 h2 = __float2bfloat16(v.z), h3 = __float2bfloat16(v.w);
                __nv_bfloat16 l0 = __float2bfloat16(v.x - __bfloat162float(h0));
                __nv_bfloat16 l1 = __float2bfloat16(v.y - __bfloat162float(h1));
                __nv_bfloat16 l2 = __float2bfloat16(v.z - __bfloat162float(h2));
                __nv_bfloat16 l3 = __float2bfloat16(v.w - __bfloat162float(h3));
                uint2 hp, lp;
                hp.x = (uint32_t)__bfloat16_as_ushort(h0) | ((uint32_t)__bfloat16_as_ushort(h1) << 16);
                hp.y = (uint32_t)__bfloat16_as_ushort(h2) | ((uint32_t)__bfloat16_as_ushort(h3) << 16);
                lp.x = (uint32_t)__bfloat16_as_ushort(l0) | ((uint32_t)__bfloat16_as_ushort(l1) << 16);
                lp.y = (uint32_t)__bfloat16_as_ushort(l2) | ((uint32_t)__bfloat16_as_ushort(l3) << 16);
                uint32_t off = (uint32_t)(r * TSTRIDE + c4 * 8);
                *(uint2*)(smem + SM_XH + off) = hp;
                *(uint2*)(smem + SM_XL + off) = lp;
            }
            // W tiles: 128 n-rows x 64 bf16 (hi and lo)
#pragma unroll
            for (int it = 0; it < 4; it++) {
                int idx = tid + it * 256;       // 0..1023 uint4s
                int r = idx >> 3, c8 = idx & 7;
                uint32_t off = (uint32_t)(r * TSTRIDE + c8 * 16);
                size_t g = (size_t)(nb * 128 + r) * Hd + kb + c8 * 8;
                *(uint4*)(smem + SM_WH + off) = *(const uint4*)&g_Whi[g];
                *(uint4*)(smem + SM_WL + off) = *(const uint4*)&g_Wlo[g];
            }
            __syncthreads();

#pragma unroll
            for (int pass = 0; pass < 3; pass++) {
                const uint32_t xbase = sb + (pass == 2 ? SM_XL : SM_XH);
                const uint32_t wbase = sb + (pass == 1 ? SM_WL : SM_WH);
#pragma unroll
                for (int k16 = 0; k16 < 4; k16++) {
                    uint32_t a[2][4];
#pragma unroll
                    for (int mi = 0; mi < 2; mi++) {
                        uint32_t addr = xbase +
                            (uint32_t)(warp_m * 32 + mi * 16 + a_row) * TSTRIDE +
                            (uint32_t)(k16 * 32) + a_colb;
                        ldsm_x4(a[mi][0], a[mi][1], a[mi][2], a[mi][3], addr);
                    }
                    uint32_t b[8][2];
#pragma unroll
                    for (int np = 0; np < 4; np++) {
                        uint32_t r0, r1, r2, r3;
                        uint32_t addr = wbase +
                            (uint32_t)(warp_n * 64 + np * 16 + b_row) * TSTRIDE +
                            (uint32_t)(k16 * 32) + b_colb;
                        ldsm_x4(r0, r1, r2, r3, addr);
                        b[np * 2][0] = r0; b[np * 2][1] = r2;
                        b[np * 2 + 1][0] = r1; b[np * 2 + 1][1] = r3;
                    }
#pragma unroll
                    for (int mi = 0; mi < 2; mi++)
#pragma unroll
                        for (int ni = 0; ni < 8; ni++)
                            mma16816(acc[mi][ni], a[mi], b[ni]);
                }
            }
            __syncthreads();
        }

        // fused epilogue for this 128-wide N chunk
#pragma unroll
        for (int mi = 0; mi < 2; mi++)
#pragma unroll
            for (int ni = 0; ni < 8; ni++) {
                int n0 = nb * 128 + warp_n * 64 + ni * 8 + (lane & 3) * 2;
                float bs0 = bs_s[n0], bs1 = bs_s[n0 + 1];
                float va0 = va_s[n0], va1 = va_s[n0 + 1];
                rowpart[mi][0] = fmaf(tanhf(acc[mi][ni][0] + bs0), va0, rowpart[mi][0]);
                rowpart[mi][0] = fmaf(tanhf(acc[mi][ni][1] + bs1), va1, rowpart[mi][0]);
                rowpart[mi][1] = fmaf(tanhf(acc[mi][ni][2] + bs0), va0, rowpart[mi][1]);
                rowpart[mi][1] = fmaf(tanhf(acc[mi][ni][3] + bs1), va1, rowpart[mi][1]);
            }
    }

    // reduce across the 4 lanes sharing each row, then across warps via smem
#pragma unroll
    for (int mi = 0; mi < 2; mi++)
#pragma unroll
        for (int rh = 0; rh < 2; rh++) {
            float v = rowpart[mi][rh];
            v += __shfl_xor_sync(0xffffffff, v, 1);
            v += __shfl_xor_sync(0xffffffff, v, 2);
            if ((lane & 3) == 0) {
                int row = warp_m * 32 + mi * 16 + rh * 8 + (lane >> 2);
                atomicAdd(&red[row], v);
            }
        }
    __syncthreads();
    if (tid < BM) g_score[row0 + tid] = red[tid] + Va_b[0];
}

// ---------------------------------------------------------------------------
// Kernel 3: softmax over T per batch row.
// ---------------------------------------------------------------------------
__global__ __launch_bounds__(256)
void softmax_kernel(float* __restrict__ out_w) {
    __shared__ float sred[256];
    const int b = blockIdx.x, tid = threadIdx.x;
    const float* s = g_score + (size_t)b * Td;
    float* w = out_w + (size_t)b * Td;

    float m = -1e30f;
    for (int t = tid; t < Td; t += 256) m = fmaxf(m, s[t]);
    sred[tid] = m; __syncthreads();
    for (int o = 128; o > 0; o >>= 1) {
        if (tid < o) sred[tid] = fmaxf(sred[tid], sred[tid + o]);
        __syncthreads();
    }
    m = sred[0]; __syncthreads();

    float sum = 0.f;
    for (int t = tid; t < Td; t += 256) {
        float e = __expf(s[t] - m);
        w[t] = e; sum += e;
    }
    sred[tid] = sum; __syncthreads();
    for (int o = 128; o > 0; o >>= 1) {
        if (tid < o) sred[tid] += sred[tid + o];
        __syncthreads();
    }
    float inv = 1.f / sred[0];
    for (int t = tid; t < Td; t += 256) w[t] *= inv;
}

// ---------------------------------------------------------------------------
// Kernel 4: context[b,h] = sum_t w[b,t] * x[b,t,h]
// ---------------------------------------------------------------------------
__global__ __launch_bounds__(256)
void context_kernel(const float* __restrict__ x, const float* __restrict__ w,
                    float* __restrict__ ctx) {
    __shared__ float ws_[Td];
    const int b = blockIdx.y;
    const int h = blockIdx.x * 256 + threadIdx.x;
    for (int t = threadIdx.x; t < Td; t += 256)
        ws_[t] = w[(size_t)b * Td + t];
    __syncthreads();
    const float* xb = x + (size_t)b * Td * Hd + h;
    float a0 = 0.f, a1 = 0.f, a2 = 0.f, a3 = 0.f;
    for (int t = 0; t < Td; t += 4) {
        a0 = fmaf(ws_[t + 0], xb[(size_t)(t + 0) * Hd], a0);
        a1 = fmaf(ws_[t + 1], xb[(size_t)(t + 1) * Hd], a1);
        a2 = fmaf(ws_[t + 2], xb[(size_t)(t + 2) * Hd], a2);
        a3 = fmaf(ws_[t + 3], xb[(size_t)(t + 3) * Hd], a3);
    }
    ctx[(size_t)b * Hd + h] = ((a0 + a1) + (a2 + a3));
}

// ---------------------------------------------------------------------------
// Launch
// ---------------------------------------------------------------------------
extern "C" void kernel_launch(void* const* d_in, const int* in_sizes, int n_in,
                              void* d_out, int out_size) {
    const float* x    = (const float*)d_in[0];
    const float* Wa_w = (const float*)d_in[1];
    const float* Wa_b = (const float*)d_in[2];
    const float* Ua_w = (const float*)d_in[3];
    const float* Ua_b = (const float*)d_in[4];
    const float* Va_w = (const float*)d_in[5];
    const float* Va_b = (const float*)d_in[6];

    float* out_ctx = (float*)d_out;             // [B,H]
    float* out_w   = (float*)d_out + Bd * Hd;   // [B,T]

    cudaFuncSetAttribute(score_mma, cudaFuncAttributeMaxDynamicSharedMemorySize,
                         SMEM_TOTAL);

    prep_kernel<<<(Hd * Hd + 255) / 256, 256>>>(Wa_w, Ua_w, Wa_b, Ua_b);
    score_mma<<<Md / BM, 256, SMEM_TOTAL>>>(x, Va_w, Va_b);
    softmax_kernel<<<Bd, 256>>>(out_w);
    context_kernel<<<dim3(Hd / 256, Bd), 256>>>(x, out_w, out_ctx);
}